// round 4
// baseline (speedup 1.0000x reference)
#include <cuda_runtime.h>
#include <math.h>

typedef unsigned long long ull;

constexpr int NNODE = 10000;
constexpr int NEDGE = 160000;
constexpr int C = 32;
constexpr int H = 64;
constexpr int F_OFF1 = NNODE * C;
constexpr int F_OFF2 = 4 * NNODE * C;
constexpr int F_OFF3 = 9 * NNODE * C;
constexpr int FTOT   = 16 * NNODE * C;

// ---------------- scratch ---------------------------------------------------
__device__ float  g_h [(size_t)NEDGE * H];
__device__ float  g_w [(size_t)NEDGE * 384];
__device__ float  g_ew[(size_t)NEDGE * 128];
__device__ float  g_sh[(size_t)NEDGE * 16];
__device__ float2 g_geo[NEDGE];
__device__ float  g_f[2][FTOT];
__device__ int    g_cnt[NNODE];
__device__ int    g_fill[NNODE];
__device__ int    g_rowstart[NNODE + 1];
__device__ int    g_src[NEDGE];
__device__ int    g_dst[NEDGE];
__device__ int    g_orig[NEDGE];

__device__ __forceinline__ float siluf(float x) { return x / (1.0f + expf(-x)); }

__device__ __forceinline__ ull dup2(float a) {
    ull r;
    asm("mov.b64 %0, {%1, %1};" : "=l"(r) : "r"(__float_as_uint(a)));
    return r;
}
__device__ __forceinline__ void ffma2(ull& d, ull a, ull b) {
    asm("fma.rn.f32x2 %0, %1, %2, %0;" : "+l"(d) : "l"(a), "l"(b));
}
__device__ __forceinline__ float2 unpack2(ull v) {
    float2 f;
    asm("mov.b64 {%0, %1}, %2;" : "=f"(f.x), "=f"(f.y) : "l"(v));
    return f;
}

// ---------------- sorting: counting sort by dst ----------------------------
__global__ void k_zero_sort() {
    int i = blockIdx.x * 256 + threadIdx.x;
    if (i < NNODE) { g_cnt[i] = 0; g_fill[i] = 0; }
}
__global__ void k_count(const int* __restrict__ ei) {
    int e = blockIdx.x * 256 + threadIdx.x;
    atomicAdd(&g_cnt[ei[NEDGE + e]], 1);
}
__global__ void k_scan() {
    __shared__ int part[1024];
    int t = threadIdx.x;
    int base = t * 10;
    int vals[10];
    int s = 0;
#pragma unroll
    for (int i = 0; i < 10; i++) {
        int idx = base + i;
        int v = (idx < NNODE) ? g_cnt[idx] : 0;
        vals[i] = s; s += v;
    }
    part[t] = s;
    __syncthreads();
    for (int d = 1; d < 1024; d <<= 1) {
        int v = (t >= d) ? part[t - d] : 0;
        __syncthreads();
        part[t] += v;
        __syncthreads();
    }
    int off = (t == 0) ? 0 : part[t - 1];
#pragma unroll
    for (int i = 0; i < 10; i++) {
        int idx = base + i;
        if (idx < NNODE) g_rowstart[idx] = off + vals[i];
    }
    if (t == 1023) g_rowstart[NNODE] = part[1023];
}

__global__ void k_fillgeom(const float* __restrict__ pos, const int* __restrict__ ei) {
    int e = blockIdx.x * 256 + threadIdx.x;
    int s = ei[e], d = ei[NEDGE + e];
    int p = g_rowstart[d] + atomicAdd(&g_fill[d], 1);
    g_src[p] = s; g_dst[p] = d; g_orig[p] = e;
    float ax = pos[3 * s], ay = pos[3 * s + 1], az = pos[3 * s + 2];
    float bx = pos[3 * d], by = pos[3 * d + 1], bz = pos[3 * d + 2];
    float vx = bx - ax, vy = by - ay, vz = bz - az;
    float r = sqrtf(vx * vx + vy * vy + vz * vz + 1e-12f);
    float u = fminf(r * (1.0f / 5.0f), 1.0f);
    float env = 0.5f * (cospif(u) + 1.0f);
    g_geo[p] = make_float2(u, env * 0.63245553203f / r);
    float inv = 1.0f / r;
    float x = vx * inv, y = vy * inv, z = vz * inv;
    float x2 = x * x, y2 = y * y, z2 = z * z;
    float4* shp = reinterpret_cast<float4*>(g_sh + (size_t)p * 16);
    shp[0] = make_float4(1.0f, 1.7320508f * x, 1.7320508f * y, 1.7320508f * z);
    shp[1] = make_float4(3.87298335f * x * y, 3.87298335f * y * z,
                         1.11803399f * (3.0f * z2 - 1.0f), 3.87298335f * x * z);
    shp[2] = make_float4(1.93649167f * (x2 - y2),
                         2.09165007f * y * (3.0f * x2 - y2),
                         10.2469508f * x * y * z,
                         1.62018517f * y * (5.0f * z2 - 1.0f));
    shp[3] = make_float4(1.32287566f * (5.0f * z2 * z - 3.0f * z),
                         1.62018517f * x * (5.0f * z2 - 1.0f),
                         5.12347538f * z * (x2 - y2),
                         2.09165007f * x * (x2 - 3.0f * y2));
}

// ---------------- K2: h = silu(rb @ rw1 + rb1) ------------------------------
// rb fill via sine recurrence: 2 sincospif anchors per 16-term run.
__global__ __launch_bounds__(256) void k_gemm1(const float* __restrict__ rw1,
                                               const float* __restrict__ rb1) {
    __shared__ float  sA[64][65];
    __shared__ float  sW[64][64];
    __shared__ float2 sG[64];
    int t  = threadIdx.x;
    int e0 = blockIdx.x * 64;
    if (t < 64) sG[t] = g_geo[e0 + t];
    ull acc[4][2];
#pragma unroll
    for (int i = 0; i < 4; i++) { acc[i][0] = 0ull; acc[i][1] = 0ull; }
    int row  = t & 63;        // A-fill: thread covers 16 consecutive n for one row
    int half = t >> 6;        // 0..3
    int jW = t & 63, kWb = t >> 6;
    int r0 = (t >> 4) << 2;
    int j0 = (t & 15) << 2;
    __syncthreads();          // sG visible
    float2 gg = sG[row];
    float s1, c1;
    sincospif(gg.x, &s1, &c1);
    float two = 2.0f * c1;
    for (int kk = 0; kk < 128; kk += 64) {
        if (kk) __syncthreads();
        {   // fill A chunk [kk, kk+64) via recurrence
            int n0 = kk + half * 16 + 1;
            float sa, ca;
            sincospif((float)n0 * gg.x, &sa, &ca);
            float sb = sa * c1 + ca * s1;   // sin((n0+1) pi u)
            int kloc = half * 16;
#pragma unroll
            for (int i = 0; i < 16; i++) {
                sA[kloc + i][row] = gg.y * sa;
                float sn = fmaf(two, sb, -sa);
                sa = sb; sb = sn;
            }
        }
#pragma unroll
        for (int i = 0; i < 16; i++) {
            int kr = kWb + (i << 2);
            sW[kr][jW] = rw1[(kk + kr) * 64 + jW];
        }
        __syncthreads();
#pragma unroll 8
        for (int k = 0; k < 64; k++) {
            ull A0 = dup2(sA[k][r0]);
            ull A1 = dup2(sA[k][r0 + 1]);
            ull A2 = dup2(sA[k][r0 + 2]);
            ull A3 = dup2(sA[k][r0 + 3]);
            const ull* bp = reinterpret_cast<const ull*>(&sW[k][j0]);
            ull b0 = bp[0], b1 = bp[1];
            ffma2(acc[0][0], A0, b0); ffma2(acc[0][1], A0, b1);
            ffma2(acc[1][0], A1, b0); ffma2(acc[1][1], A1, b1);
            ffma2(acc[2][0], A2, b0); ffma2(acc[2][1], A2, b1);
            ffma2(acc[3][0], A3, b0); ffma2(acc[3][1], A3, b1);
        }
    }
    float4 bias = *reinterpret_cast<const float4*>(&rb1[j0]);
#pragma unroll
    for (int i = 0; i < 4; i++) {
        float2 lo = unpack2(acc[i][0]), hi = unpack2(acc[i][1]);
        float4 o;
        o.x = siluf(lo.x + bias.x); o.y = siluf(lo.y + bias.y);
        o.z = siluf(hi.x + bias.z); o.w = siluf(hi.y + bias.w);
        *reinterpret_cast<float4*>(&g_h[(size_t)(e0 + r0 + i) * 64 + j0]) = o;
    }
}

// ---------------- K3: [w_all | ew] = h @ [rw2 | edge_w] + bias -------------
__global__ __launch_bounds__(256) void k_gemm2(const float* __restrict__ rw2,
                                               const float* __restrict__ rb2,
                                               const float* __restrict__ edge_w,
                                               const float* __restrict__ edge_b) {
    __shared__ float sH[32][66];
    __shared__ float sW2[32][256];
    int t  = threadIdx.x;
    int e0 = blockIdx.x * 64;
    int cb = blockIdx.y << 8;
    int lane = t & 31;
    int r0 = lane << 1;
    int j0 = (t >> 5) << 5;
    ull acc[2][16];
#pragma unroll
    for (int i = 0; i < 2; i++)
#pragma unroll
        for (int j = 0; j < 16; j++) acc[i][j] = 0ull;
    int kh = t & 31, rb_ = (t >> 5) << 3;
    int colg = cb + t;
    for (int kk = 0; kk < 64; kk += 32) {
        __syncthreads();
#pragma unroll
        for (int i = 0; i < 8; i++)
            sH[kh][rb_ + i] = g_h[(size_t)(e0 + rb_ + i) * 64 + kk + kh];
#pragma unroll
        for (int kr = 0; kr < 32; kr++) {
            sW2[kr][t] = (colg < 384) ? rw2[(kk + kr) * 384 + colg]
                                      : edge_w[(kk + kr) * 128 + colg - 384];
        }
        __syncthreads();
#pragma unroll
        for (int k = 0; k < 32; k++) {
            ull a01 = *reinterpret_cast<const ull*>(&sH[k][r0]);
            float2 af = unpack2(a01);
            ull A0 = dup2(af.x), A1 = dup2(af.y);
            const ull* bp = reinterpret_cast<const ull*>(&sW2[k][j0]);
#pragma unroll
            for (int j = 0; j < 16; j++) {
                ull b = bp[j];
                ffma2(acc[0][j], A0, b);
                ffma2(acc[1][j], A1, b);
            }
        }
    }
    bool inw = (cb + j0) < 384;
    const float* bsrc = inw ? (rb2 + cb + j0) : (edge_b + cb + j0 - 384);
#pragma unroll
    for (int i = 0; i < 2; i++) {
        int row = e0 + r0 + i;
        float* base = inw ? (g_w + (size_t)row * 384 + cb + j0)
                          : (g_ew + (size_t)row * 128 + cb + j0 - 384);
#pragma unroll
        for (int j = 0; j < 8; j++) {
            float2 p0 = unpack2(acc[i][2 * j]);
            float2 p1 = unpack2(acc[i][2 * j + 1]);
            float4 o = make_float4(p0.x + bsrc[4 * j],     p0.y + bsrc[4 * j + 1],
                                   p1.x + bsrc[4 * j + 2], p1.y + bsrc[4 * j + 3]);
            *reinterpret_cast<float4*>(base + 4 * j) = o;
        }
    }
}

// ---------------- init f[0] -------------------------------------------------
__global__ void k_initf(const float* __restrict__ node_embed,
                        const int* __restrict__ species) {
    int i4 = blockIdx.x * 256 + threadIdx.x;
    int idx = i4 * 4;
    float4 v;
    if (idx < NNODE * C) {
        int n = idx >> 5, c = idx & 31;
        v = *reinterpret_cast<const float4*>(&node_embed[(species[n] << 5) + c]);
    } else {
        v = make_float4(0.f, 0.f, 0.f, 0.f);
    }
    *reinterpret_cast<float4*>(&g_f[0][idx]) = v;
}

// ---------------- K4: gather-aggregate + node update (task-parallel) -------
// Block = 8 nodes. Phase 1: warp-per-node gather into acc regs + sAg.
// Phase 2a: l0 update + gate (shfl matvec, small). Phase 2b: 120 (node,l,m)
// matvec tasks split 15/warp, W columns cached in registers, inputs read as
// uniform float4 broadcasts.
__global__ __launch_bounds__(256) void k_msgnode(const float* __restrict__ self_w,
                                                 const float* __restrict__ msg_w,
                                                 const float* __restrict__ gate_w,
                                                 int t, int cur,
                                                 float* __restrict__ out) {
    __shared__ float sS0[1024];
    __shared__ float sM0[1024];
    __shared__ float sAg[8][16][32];
    __shared__ float sGate[8][32];
    int tid = threadIdx.x;
    for (int i = tid; i < 1024; i += 256) {
        sS0[i] = self_w[t * 4096 + i];
        sM0[i] = msg_w[t * 4096 + i];
    }
    int lane = tid & 31;
    int w = tid >> 5;
    int n = blockIdx.x * 8 + w;
    const float* fin = g_f[cur];
    float* fout = g_f[cur ^ 1];
    __syncthreads();

    // ---- phase 1: gather-aggregate ----
    float acc[16];
#pragma unroll
    for (int i = 0; i < 16; i++) acc[i] = 0.0f;
    int row0 = g_rowstart[n], row1 = g_rowstart[n + 1];
#pragma unroll 2
    for (int row = row0; row < row1; row++) {
        float sv = fin[g_src[row] * C + lane];
        const float* wr = g_w + (size_t)row * 384 + t * 128;
        float w0 = wr[lane] * sv;
        float w1 = wr[32 + lane] * sv;
        float w2 = wr[64 + lane] * sv;
        float w3 = wr[96 + lane] * sv;
        const float4* shp = reinterpret_cast<const float4*>(g_sh + (size_t)row * 16);
        float4 s0 = shp[0], s1 = shp[1], s2 = shp[2], s3 = shp[3];
        acc[0]  += w0;
        acc[1]  = fmaf(w1, s0.y, acc[1]);
        acc[2]  = fmaf(w1, s0.z, acc[2]);
        acc[3]  = fmaf(w1, s0.w, acc[3]);
        acc[4]  = fmaf(w2, s1.x, acc[4]);
        acc[5]  = fmaf(w2, s1.y, acc[5]);
        acc[6]  = fmaf(w2, s1.z, acc[6]);
        acc[7]  = fmaf(w2, s1.w, acc[7]);
        acc[8]  = fmaf(w2, s2.x, acc[8]);
        acc[9]  = fmaf(w3, s2.y, acc[9]);
        acc[10] = fmaf(w3, s2.z, acc[10]);
        acc[11] = fmaf(w3, s2.w, acc[11]);
        acc[12] = fmaf(w3, s3.x, acc[12]);
        acc[13] = fmaf(w3, s3.y, acc[13]);
        acc[14] = fmaf(w3, s3.z, acc[14]);
        acc[15] = fmaf(w3, s3.w, acc[15]);
    }
#pragma unroll
    for (int mi = 0; mi < 16; mi++) sAg[w][mi][lane] = acc[mi];

    // ---- phase 2a: l0 update + gate ----
    float fv = fin[n * C + lane];
    float a0 = 0.0f;
#pragma unroll
    for (int c = 0; c < 32; c++) {
        a0 = fmaf(__shfl_sync(0xffffffffu, fv, c), sS0[c * 32 + lane], a0);
        a0 = fmaf(__shfl_sync(0xffffffffu, acc[0], c), sM0[c * 32 + lane], a0);
    }
    float ga = 0.0f;
    const float* gw = gate_w + t * 1024;
#pragma unroll
    for (int c = 0; c < 32; c++)
        ga = fmaf(__shfl_sync(0xffffffffu, a0, c), gw[c * 32 + lane], ga);
    float gate = 1.0f / (1.0f + expf(-ga));
    float s0v = siluf(a0);
    fout[n * C + lane] = s0v;
    if (t == 2) out[(size_t)n * 512 + lane] = s0v;
    sGate[w][lane] = gate;
    __syncthreads();

    // ---- phase 2b: 120 tasks, 15 per warp ----
    float wS[32], wM[32];
    int curl = 0;
    int T0 = w * 15;
#pragma unroll 1
    for (int i = 0; i < 15; i++) {
        int T = T0 + i;
        int l, nl, m;
        if (T < 24)      { l = 1; nl = T / 3;  m = T - 3 * nl; }
        else if (T < 64) { int q = T - 24; l = 2; nl = q / 5; m = q - 5 * nl; }
        else             { int q = T - 64; l = 3; nl = q / 7; m = q - 7 * nl; }
        if (l != curl) {
            curl = l;
            const float* ws = self_w + t * 4096 + l * 1024 + lane;
            const float* wm = msg_w  + t * 4096 + l * 1024 + lane;
#pragma unroll
            for (int c = 0; c < 32; c++) { wS[c] = ws[c * 32]; wM[c] = wm[c * 32]; }
        }
        int dl   = 2 * l + 1;
        int offs = (l == 1) ? F_OFF1 : (l == 2) ? F_OFF2 : F_OFF3;
        int mi   = (l == 1) ? 1 + m : (l == 2) ? 4 + m : 9 + m;
        int gn   = blockIdx.x * 8 + nl;
        int base = offs + (gn * dl + m) * C;
        const float4* frow = reinterpret_cast<const float4*>(fin + base);
        const float4* arow = reinterpret_cast<const float4*>(&sAg[nl][mi][0]);
        float a = 0.0f;
#pragma unroll
        for (int c4 = 0; c4 < 8; c4++) {
            float4 f4 = frow[c4];
            float4 a4 = arow[c4];
            a = fmaf(f4.x, wS[4 * c4],     a);
            a = fmaf(a4.x, wM[4 * c4],     a);
            a = fmaf(f4.y, wS[4 * c4 + 1], a);
            a = fmaf(a4.y, wM[4 * c4 + 1], a);
            a = fmaf(f4.z, wS[4 * c4 + 2], a);
            a = fmaf(a4.z, wM[4 * c4 + 2], a);
            a = fmaf(f4.w, wS[4 * c4 + 3], a);
            a = fmaf(a4.w, wM[4 * c4 + 3], a);
        }
        float res = a * sGate[nl][lane];
        if (t < 2) {
            fout[base + lane] = res;
        } else {
            int colb = (l == 1) ? 32 : (l == 2) ? 128 : 288;
            out[(size_t)gn * 512 + colb + lane * dl + m] = res;
        }
    }
}

// ---------------- edge output: warp per edge, lane = channel ----------------
__global__ __launch_bounds__(256) void k_edgeout(float* __restrict__ out, int cur) {
    int lane = threadIdx.x & 31;
    int e = blockIdx.x * 8 + (threadIdx.x >> 5);
    int s = g_src[e], d = g_dst[e];
    const float* f0 = g_f[cur];
    float gv = f0[s * C + lane] + f0[d * C + lane];
    const float* ewp = g_ew + (size_t)e * 128;
    float ew0 = ewp[lane], ew1 = ewp[32 + lane], ew2 = ewp[64 + lane], ew3 = ewp[96 + lane];
    const float4* shp = reinterpret_cast<const float4*>(g_sh + (size_t)e * 16);
    float4 s0 = shp[0], s1 = shp[1], s2 = shp[2], s3 = shp[3];
    float* base = out + (size_t)(NNODE + g_orig[e]) * 512;
    base[lane] = ew0 * gv;
    float w1 = ew1 * gv;
    float* p1 = base + 32 + lane * 3;
    p1[0] = w1 * s0.y; p1[1] = w1 * s0.z; p1[2] = w1 * s0.w;
    float w2 = ew2 * gv;
    float* p2 = base + 128 + lane * 5;
    p2[0] = w2 * s1.x; p2[1] = w2 * s1.y; p2[2] = w2 * s1.z;
    p2[3] = w2 * s1.w; p2[4] = w2 * s2.x;
    float w3 = ew3 * gv;
    float* p3 = base + 288 + lane * 7;
    p3[0] = w3 * s2.y; p3[1] = w3 * s2.z; p3[2] = w3 * s2.w;
    p3[3] = w3 * s3.x; p3[4] = w3 * s3.y; p3[5] = w3 * s3.z; p3[6] = w3 * s3.w;
}

// ---------------- launch ----------------------------------------------------
extern "C" void kernel_launch(void* const* d_in, const int* in_sizes, int n_in,
                              void* d_out, int out_size) {
    const float* pos        = (const float*)d_in[0];
    const float* node_embed = (const float*)d_in[1];
    const float* rw1        = (const float*)d_in[2];
    const float* rb1        = (const float*)d_in[3];
    const float* rw2        = (const float*)d_in[4];
    const float* rb2        = (const float*)d_in[5];
    const float* self_w     = (const float*)d_in[6];
    const float* msg_w      = (const float*)d_in[7];
    const float* gate_w     = (const float*)d_in[8];
    const float* edge_w     = (const float*)d_in[9];
    const float* edge_b     = (const float*)d_in[10];
    const int*   species    = (const int*)d_in[11];
    const int*   ei         = (const int*)d_in[12];
    float* out = (float*)d_out;

    k_zero_sort<<<(NNODE + 255) / 256, 256>>>();
    k_count<<<NEDGE / 256, 256>>>(ei);
    k_scan<<<1, 1024>>>();
    k_fillgeom<<<NEDGE / 256, 256>>>(pos, ei);
    k_gemm1<<<NEDGE / 64, 256>>>(rw1, rb1);
    dim3 g2(NEDGE / 64, 2);
    k_gemm2<<<g2, 256>>>(rw2, rb2, edge_w, edge_b);
    k_initf<<<FTOT / 4 / 256, 256>>>(node_embed, species);

    int cur = 0;
    for (int t = 0; t < 3; t++) {
        k_msgnode<<<NNODE / 8, 256>>>(self_w, msg_w, gate_w, t, cur, out);
        cur ^= 1;
    }

    k_edgeout<<<NEDGE / 8, 256>>>(out, cur);
}

// round 5
// speedup vs baseline: 1.2635x; 1.2635x over previous
#include <cuda_runtime.h>
#include <math.h>

typedef unsigned long long ull;

constexpr int NNODE = 10000;
constexpr int NEDGE = 160000;
constexpr int C = 32;
constexpr int H = 64;
constexpr int F_OFF1 = NNODE * C;
constexpr int F_OFF2 = 4 * NNODE * C;
constexpr int F_OFF3 = 9 * NNODE * C;
constexpr int FTOT   = 16 * NNODE * C;

// ---------------- scratch ---------------------------------------------------
__device__ float  g_h [(size_t)NEDGE * H];
__device__ float  g_w [(size_t)NEDGE * 384];
__device__ float  g_ew[(size_t)NEDGE * 128];
__device__ float  g_sh[(size_t)NEDGE * 16];
__device__ float2 g_geo[NEDGE];
__device__ float  g_f[2][FTOT];
__device__ float  g_agg[FTOT];
__device__ float  g_gate[NNODE * C];
__device__ int    g_cnt[NNODE];
__device__ int    g_fill[NNODE];
__device__ int    g_rowstart[NNODE + 1];
__device__ int    g_src[NEDGE];
__device__ int    g_dst[NEDGE];
__device__ int    g_orig[NEDGE];

__device__ __forceinline__ float siluf(float x) { return x / (1.0f + expf(-x)); }

__device__ __forceinline__ ull dup2(float a) {
    ull r;
    asm("mov.b64 %0, {%1, %1};" : "=l"(r) : "r"(__float_as_uint(a)));
    return r;
}
__device__ __forceinline__ void ffma2(ull& d, ull a, ull b) {
    asm("fma.rn.f32x2 %0, %1, %2, %0;" : "+l"(d) : "l"(a), "l"(b));
}
__device__ __forceinline__ float2 unpack2(ull v) {
    float2 f;
    asm("mov.b64 {%0, %1}, %2;" : "=f"(f.x), "=f"(f.y) : "l"(v));
    return f;
}

// ---------------- sorting: counting sort by dst ----------------------------
__global__ void k_zero_sort() {
    int i = blockIdx.x * 256 + threadIdx.x;
    if (i < NNODE) { g_cnt[i] = 0; g_fill[i] = 0; }
}
__global__ void k_count(const int* __restrict__ ei) {
    int e = blockIdx.x * 256 + threadIdx.x;
    atomicAdd(&g_cnt[ei[NEDGE + e]], 1);
}
__global__ void k_scan() {
    __shared__ int part[1024];
    int t = threadIdx.x;
    int base = t * 10;
    int vals[10];
    int s = 0;
#pragma unroll
    for (int i = 0; i < 10; i++) {
        int idx = base + i;
        int v = (idx < NNODE) ? g_cnt[idx] : 0;
        vals[i] = s; s += v;
    }
    part[t] = s;
    __syncthreads();
    for (int d = 1; d < 1024; d <<= 1) {
        int v = (t >= d) ? part[t - d] : 0;
        __syncthreads();
        part[t] += v;
        __syncthreads();
    }
    int off = (t == 0) ? 0 : part[t - 1];
#pragma unroll
    for (int i = 0; i < 10; i++) {
        int idx = base + i;
        if (idx < NNODE) g_rowstart[idx] = off + vals[i];
    }
    if (t == 1023) g_rowstart[NNODE] = part[1023];
}

__global__ void k_fillgeom(const float* __restrict__ pos, const int* __restrict__ ei) {
    int e = blockIdx.x * 256 + threadIdx.x;
    int s = ei[e], d = ei[NEDGE + e];
    int p = g_rowstart[d] + atomicAdd(&g_fill[d], 1);
    g_src[p] = s; g_dst[p] = d; g_orig[p] = e;
    float ax = pos[3 * s], ay = pos[3 * s + 1], az = pos[3 * s + 2];
    float bx = pos[3 * d], by = pos[3 * d + 1], bz = pos[3 * d + 2];
    float vx = bx - ax, vy = by - ay, vz = bz - az;
    float r = sqrtf(vx * vx + vy * vy + vz * vz + 1e-12f);
    float u = fminf(r * (1.0f / 5.0f), 1.0f);
    float env = 0.5f * (cospif(u) + 1.0f);
    g_geo[p] = make_float2(u, env * 0.63245553203f / r);
    float inv = 1.0f / r;
    float x = vx * inv, y = vy * inv, z = vz * inv;
    float x2 = x * x, y2 = y * y, z2 = z * z;
    float4* shp = reinterpret_cast<float4*>(g_sh + (size_t)p * 16);
    shp[0] = make_float4(1.0f, 1.7320508f * x, 1.7320508f * y, 1.7320508f * z);
    shp[1] = make_float4(3.87298335f * x * y, 3.87298335f * y * z,
                         1.11803399f * (3.0f * z2 - 1.0f), 3.87298335f * x * z);
    shp[2] = make_float4(1.93649167f * (x2 - y2),
                         2.09165007f * y * (3.0f * x2 - y2),
                         10.2469508f * x * y * z,
                         1.62018517f * y * (5.0f * z2 - 1.0f));
    shp[3] = make_float4(1.32287566f * (5.0f * z2 * z - 3.0f * z),
                         1.62018517f * x * (5.0f * z2 - 1.0f),
                         5.12347538f * z * (x2 - y2),
                         2.09165007f * x * (x2 - 3.0f * y2));
}

// ---------------- K2: h = silu(rb @ rw1 + rb1), recurrence fill ------------
__global__ __launch_bounds__(256) void k_gemm1(const float* __restrict__ rw1,
                                               const float* __restrict__ rb1) {
    __shared__ float  sA[64][65];
    __shared__ float  sW[64][64];
    __shared__ float2 sG[64];
    int t  = threadIdx.x;
    int e0 = blockIdx.x * 64;
    if (t < 64) sG[t] = g_geo[e0 + t];
    ull acc[4][2];
#pragma unroll
    for (int i = 0; i < 4; i++) { acc[i][0] = 0ull; acc[i][1] = 0ull; }
    int row  = t & 63;
    int half = t >> 6;
    int jW = t & 63, kWb = t >> 6;
    int r0 = (t >> 4) << 2;
    int j0 = (t & 15) << 2;
    __syncthreads();
    float2 gg = sG[row];
    float s1, c1;
    sincospif(gg.x, &s1, &c1);
    float two = 2.0f * c1;
    for (int kk = 0; kk < 128; kk += 64) {
        if (kk) __syncthreads();
        {
            int n0 = kk + half * 16 + 1;
            float sa, ca;
            sincospif((float)n0 * gg.x, &sa, &ca);
            float sb = sa * c1 + ca * s1;
            int kloc = half * 16;
#pragma unroll
            for (int i = 0; i < 16; i++) {
                sA[kloc + i][row] = gg.y * sa;
                float sn = fmaf(two, sb, -sa);
                sa = sb; sb = sn;
            }
        }
#pragma unroll
        for (int i = 0; i < 16; i++) {
            int kr = kWb + (i << 2);
            sW[kr][jW] = rw1[(kk + kr) * 64 + jW];
        }
        __syncthreads();
#pragma unroll 8
        for (int k = 0; k < 64; k++) {
            ull A0 = dup2(sA[k][r0]);
            ull A1 = dup2(sA[k][r0 + 1]);
            ull A2 = dup2(sA[k][r0 + 2]);
            ull A3 = dup2(sA[k][r0 + 3]);
            const ull* bp = reinterpret_cast<const ull*>(&sW[k][j0]);
            ull b0 = bp[0], b1 = bp[1];
            ffma2(acc[0][0], A0, b0); ffma2(acc[0][1], A0, b1);
            ffma2(acc[1][0], A1, b0); ffma2(acc[1][1], A1, b1);
            ffma2(acc[2][0], A2, b0); ffma2(acc[2][1], A2, b1);
            ffma2(acc[3][0], A3, b0); ffma2(acc[3][1], A3, b1);
        }
    }
    float4 bias = *reinterpret_cast<const float4*>(&rb1[j0]);
#pragma unroll
    for (int i = 0; i < 4; i++) {
        float2 lo = unpack2(acc[i][0]), hi = unpack2(acc[i][1]);
        float4 o;
        o.x = siluf(lo.x + bias.x); o.y = siluf(lo.y + bias.y);
        o.z = siluf(hi.x + bias.z); o.w = siluf(hi.y + bias.w);
        *reinterpret_cast<float4*>(&g_h[(size_t)(e0 + r0 + i) * 64 + j0]) = o;
    }
}

// ---------------- K3: [w_all | ew] = h @ [rw2 | edge_w] + bias -------------
__global__ __launch_bounds__(256) void k_gemm2(const float* __restrict__ rw2,
                                               const float* __restrict__ rb2,
                                               const float* __restrict__ edge_w,
                                               const float* __restrict__ edge_b) {
    __shared__ float sH[32][66];
    __shared__ float sW2[32][256];
    int t  = threadIdx.x;
    int e0 = blockIdx.x * 64;
    int cb = blockIdx.y << 8;
    int lane = t & 31;
    int r0 = lane << 1;
    int j0 = (t >> 5) << 5;
    ull acc[2][16];
#pragma unroll
    for (int i = 0; i < 2; i++)
#pragma unroll
        for (int j = 0; j < 16; j++) acc[i][j] = 0ull;
    int kh = t & 31, rb_ = (t >> 5) << 3;
    int colg = cb + t;
    for (int kk = 0; kk < 64; kk += 32) {
        __syncthreads();
#pragma unroll
        for (int i = 0; i < 8; i++)
            sH[kh][rb_ + i] = g_h[(size_t)(e0 + rb_ + i) * 64 + kk + kh];
#pragma unroll
        for (int kr = 0; kr < 32; kr++) {
            sW2[kr][t] = (colg < 384) ? rw2[(kk + kr) * 384 + colg]
                                      : edge_w[(kk + kr) * 128 + colg - 384];
        }
        __syncthreads();
#pragma unroll
        for (int k = 0; k < 32; k++) {
            ull a01 = *reinterpret_cast<const ull*>(&sH[k][r0]);
            float2 af = unpack2(a01);
            ull A0 = dup2(af.x), A1 = dup2(af.y);
            const ull* bp = reinterpret_cast<const ull*>(&sW2[k][j0]);
#pragma unroll
            for (int j = 0; j < 16; j++) {
                ull b = bp[j];
                ffma2(acc[0][j], A0, b);
                ffma2(acc[1][j], A1, b);
            }
        }
    }
    bool inw = (cb + j0) < 384;
    const float* bsrc = inw ? (rb2 + cb + j0) : (edge_b + cb + j0 - 384);
#pragma unroll
    for (int i = 0; i < 2; i++) {
        int row = e0 + r0 + i;
        float* base = inw ? (g_w + (size_t)row * 384 + cb + j0)
                          : (g_ew + (size_t)row * 128 + cb + j0 - 384);
#pragma unroll
        for (int j = 0; j < 8; j++) {
            float2 p0 = unpack2(acc[i][2 * j]);
            float2 p1 = unpack2(acc[i][2 * j + 1]);
            float4 o = make_float4(p0.x + bsrc[4 * j],     p0.y + bsrc[4 * j + 1],
                                   p1.x + bsrc[4 * j + 2], p1.y + bsrc[4 * j + 3]);
            *reinterpret_cast<float4*>(base + 4 * j) = o;
        }
    }
}

// ---------------- init f[0] -------------------------------------------------
__global__ void k_initf(const float* __restrict__ node_embed,
                        const int* __restrict__ species) {
    int i4 = blockIdx.x * 256 + threadIdx.x;
    int idx = i4 * 4;
    float4 v;
    if (idx < NNODE * C) {
        int n = idx >> 5, c = idx & 31;
        v = *reinterpret_cast<const float4*>(&node_embed[(species[n] << 5) + c]);
    } else {
        v = make_float4(0.f, 0.f, 0.f, 0.f);
    }
    *reinterpret_cast<float4*>(&g_f[0][idx]) = v;
}

// ---------------- K4a: gather-aggregate + l0 update + gate -----------------
// warp per node; writes agg comps 1..15 to g_agg; l0 matvec via shfl.
__global__ __launch_bounds__(256) void k_gather(const float* __restrict__ self_w,
                                                const float* __restrict__ msg_w,
                                                const float* __restrict__ gate_w,
                                                int t, int cur,
                                                float* __restrict__ out) {
    __shared__ float sS0[1024];
    __shared__ float sM0[1024];
    __shared__ float sGw[1024];
    int tid = threadIdx.x;
    for (int i = tid; i < 1024; i += 256) {
        sS0[i] = self_w[t * 4096 + i];
        sM0[i] = msg_w[t * 4096 + i];
        sGw[i] = gate_w[t * 1024 + i];
    }
    __syncthreads();
    int lane = tid & 31;
    int n = blockIdx.x * 8 + (tid >> 5);
    const float* fin = g_f[cur];
    float* fout = g_f[cur ^ 1];

    float acc[16];
#pragma unroll
    for (int i = 0; i < 16; i++) acc[i] = 0.0f;
    int row0 = g_rowstart[n], row1 = g_rowstart[n + 1];
#pragma unroll 2
    for (int row = row0; row < row1; row++) {
        float sv = fin[g_src[row] * C + lane];
        const float* wr = g_w + (size_t)row * 384 + t * 128;
        float w0 = wr[lane] * sv;
        float w1 = wr[32 + lane] * sv;
        float w2 = wr[64 + lane] * sv;
        float w3 = wr[96 + lane] * sv;
        const float4* shp = reinterpret_cast<const float4*>(g_sh + (size_t)row * 16);
        float4 s0 = shp[0], s1 = shp[1], s2 = shp[2], s3 = shp[3];
        acc[0]  += w0;
        acc[1]  = fmaf(w1, s0.y, acc[1]);
        acc[2]  = fmaf(w1, s0.z, acc[2]);
        acc[3]  = fmaf(w1, s0.w, acc[3]);
        acc[4]  = fmaf(w2, s1.x, acc[4]);
        acc[5]  = fmaf(w2, s1.y, acc[5]);
        acc[6]  = fmaf(w2, s1.z, acc[6]);
        acc[7]  = fmaf(w2, s1.w, acc[7]);
        acc[8]  = fmaf(w2, s2.x, acc[8]);
        acc[9]  = fmaf(w3, s2.y, acc[9]);
        acc[10] = fmaf(w3, s2.z, acc[10]);
        acc[11] = fmaf(w3, s2.w, acc[11]);
        acc[12] = fmaf(w3, s3.x, acc[12]);
        acc[13] = fmaf(w3, s3.y, acc[13]);
        acc[14] = fmaf(w3, s3.z, acc[14]);
        acc[15] = fmaf(w3, s3.w, acc[15]);
    }
    // write agg comps for l>=1 (layout matches g_f regions)
    float* a1 = g_agg + F_OFF1 + n * 3 * C + lane;
    a1[0] = acc[1]; a1[32] = acc[2]; a1[64] = acc[3];
    float* a2 = g_agg + F_OFF2 + n * 5 * C + lane;
    a2[0] = acc[4]; a2[32] = acc[5]; a2[64] = acc[6]; a2[96] = acc[7]; a2[128] = acc[8];
    float* a3 = g_agg + F_OFF3 + n * 7 * C + lane;
    a3[0] = acc[9]; a3[32] = acc[10]; a3[64] = acc[11]; a3[96] = acc[12];
    a3[128] = acc[13]; a3[160] = acc[14]; a3[192] = acc[15];

    // l0 update + gate
    float fv = fin[n * C + lane];
    float a0 = 0.0f;
#pragma unroll
    for (int c = 0; c < 32; c++) {
        a0 = fmaf(__shfl_sync(0xffffffffu, fv, c), sS0[c * 32 + lane], a0);
        a0 = fmaf(__shfl_sync(0xffffffffu, acc[0], c), sM0[c * 32 + lane], a0);
    }
    float ga = 0.0f;
#pragma unroll
    for (int c = 0; c < 32; c++)
        ga = fmaf(__shfl_sync(0xffffffffu, a0, c), sGw[c * 32 + lane], ga);
    float gate = 1.0f / (1.0f + expf(-ga));
    float s0v = siluf(a0);
    fout[n * C + lane] = s0v;
    g_gate[n * C + lane] = gate;
    if (t == 2) out[(size_t)n * 512 + lane] = s0v;
}

// ---------------- K4b: l>=1 node update as dense GEMM ----------------------
// rows = (node, m) pairs of one l-region; 64 rows x 32 cols per block.
constexpr int NB1 = (3 * NNODE + 63) / 64;   // 469
constexpr int NB2 = (5 * NNODE + 63) / 64;   // 782
constexpr int NB3 = (7 * NNODE + 63) / 64;   // 1094
__global__ __launch_bounds__(256) void k_nodeL(const float* __restrict__ self_w,
                                               const float* __restrict__ msg_w,
                                               int t, int cur,
                                               float* __restrict__ out) {
    __shared__ float sF[32][68];
    __shared__ float sA[32][68];
    __shared__ float sWs[32][33];
    __shared__ float sWm[32][33];
    int bid = blockIdx.x;
    int l, row0, regrows, regbase;
    if (bid < NB1)            { l = 1; row0 = bid * 64;               regrows = 3 * NNODE; regbase = F_OFF1; }
    else if (bid < NB1 + NB2) { l = 2; row0 = (bid - NB1) * 64;       regrows = 5 * NNODE; regbase = F_OFF2; }
    else                      { l = 3; row0 = (bid - NB1 - NB2) * 64; regrows = 7 * NNODE; regbase = F_OFF3; }
    int tid = threadIdx.x;
    const float* fin = g_f[cur];
    float* fout = g_f[cur ^ 1];
    for (int i = tid; i < 1024; i += 256) {
        int c = i >> 5, d = i & 31;
        sWs[c][d] = self_w[t * 4096 + l * 1024 + i];
        sWm[c][d] = msg_w [t * 4096 + l * 1024 + i];
    }
    int nrows = min(64, regrows - row0);
    {   // load + transpose tiles: thread -> (row = tid>>2, kh = tid&3)
        int trow = tid >> 2, kh = tid & 3;
        float4 z = make_float4(0.f, 0.f, 0.f, 0.f);
        float4 v0 = z, v1 = z, w0 = z, w1 = z;
        if (trow < nrows) {
            const float4* fp = reinterpret_cast<const float4*>(fin + regbase + (size_t)(row0 + trow) * 32);
            const float4* ap = reinterpret_cast<const float4*>(g_agg + regbase + (size_t)(row0 + trow) * 32);
            v0 = fp[kh]; v1 = fp[kh + 4];
            w0 = ap[kh]; w1 = ap[kh + 4];
        }
        int k0 = kh * 4;
        sF[k0][trow] = v0.x; sF[k0 + 1][trow] = v0.y; sF[k0 + 2][trow] = v0.z; sF[k0 + 3][trow] = v0.w;
        sF[k0 + 16][trow] = v1.x; sF[k0 + 17][trow] = v1.y; sF[k0 + 18][trow] = v1.z; sF[k0 + 19][trow] = v1.w;
        sA[k0][trow] = w0.x; sA[k0 + 1][trow] = w0.y; sA[k0 + 2][trow] = w0.z; sA[k0 + 3][trow] = w0.w;
        sA[k0 + 16][trow] = w1.x; sA[k0 + 17][trow] = w1.y; sA[k0 + 18][trow] = w1.z; sA[k0 + 19][trow] = w1.w;
    }
    __syncthreads();
    int col = tid & 31, rg = tid >> 5;      // warp covers 32 cols x 8 rows
    ull acc[4] = {0ull, 0ull, 0ull, 0ull};
#pragma unroll
    for (int k = 0; k < 32; k++) {
        const ull* fa = reinterpret_cast<const ull*>(&sF[k][rg * 8]);
        const ull* aa = reinterpret_cast<const ull*>(&sA[k][rg * 8]);
        ull bs = dup2(sWs[k][col]);
        ull bm = dup2(sWm[k][col]);
        ffma2(acc[0], fa[0], bs); ffma2(acc[0], aa[0], bm);
        ffma2(acc[1], fa[1], bs); ffma2(acc[1], aa[1], bm);
        ffma2(acc[2], fa[2], bs); ffma2(acc[2], aa[2], bm);
        ffma2(acc[3], fa[3], bs); ffma2(acc[3], aa[3], bm);
    }
    int r0 = rg * 8;
#pragma unroll
    for (int p = 0; p < 4; p++) {
        float2 v = unpack2(acc[p]);
        float vv[2] = {v.x, v.y};
#pragma unroll
        for (int j = 0; j < 2; j++) {
            int lrow = r0 + 2 * p + j;
            if (lrow >= nrows) continue;
            int grow = row0 + lrow;
            int node, m;
            if (l == 1)      { node = grow / 3; m = grow - node * 3; }
            else if (l == 2) { node = grow / 5; m = grow - node * 5; }
            else             { node = grow / 7; m = grow - node * 7; }
            float res = vv[j] * g_gate[node * C + col];
            if (t < 2) {
                fout[regbase + (size_t)grow * 32 + col] = res;
            } else {
                int colb = (l == 1) ? 32 : (l == 2) ? 128 : 288;
                out[(size_t)node * 512 + colb + col * (2 * l + 1) + m] = res;
            }
        }
    }
}

// ---------------- edge output: warp per edge, lane = channel ----------------
__global__ __launch_bounds__(256) void k_edgeout(float* __restrict__ out, int cur) {
    int lane = threadIdx.x & 31;
    int e = blockIdx.x * 8 + (threadIdx.x >> 5);
    int s = g_src[e], d = g_dst[e];
    const float* f0 = g_f[cur];
    float gv = f0[s * C + lane] + f0[d * C + lane];
    const float* ewp = g_ew + (size_t)e * 128;
    float ew0 = ewp[lane], ew1 = ewp[32 + lane], ew2 = ewp[64 + lane], ew3 = ewp[96 + lane];
    const float4* shp = reinterpret_cast<const float4*>(g_sh + (size_t)e * 16);
    float4 s0 = shp[0], s1 = shp[1], s2 = shp[2], s3 = shp[3];
    float* base = out + (size_t)(NNODE + g_orig[e]) * 512;
    base[lane] = ew0 * gv;
    float w1 = ew1 * gv;
    float* p1 = base + 32 + lane * 3;
    p1[0] = w1 * s0.y; p1[1] = w1 * s0.z; p1[2] = w1 * s0.w;
    float w2 = ew2 * gv;
    float* p2 = base + 128 + lane * 5;
    p2[0] = w2 * s1.x; p2[1] = w2 * s1.y; p2[2] = w2 * s1.z;
    p2[3] = w2 * s1.w; p2[4] = w2 * s2.x;
    float w3 = ew3 * gv;
    float* p3 = base + 288 + lane * 7;
    p3[0] = w3 * s2.y; p3[1] = w3 * s2.z; p3[2] = w3 * s2.w;
    p3[3] = w3 * s3.x; p3[4] = w3 * s3.y; p3[5] = w3 * s3.z; p3[6] = w3 * s3.w;
}

// ---------------- launch ----------------------------------------------------
extern "C" void kernel_launch(void* const* d_in, const int* in_sizes, int n_in,
                              void* d_out, int out_size) {
    const float* pos        = (const float*)d_in[0];
    const float* node_embed = (const float*)d_in[1];
    const float* rw1        = (const float*)d_in[2];
    const float* rb1        = (const float*)d_in[3];
    const float* rw2        = (const float*)d_in[4];
    const float* rb2        = (const float*)d_in[5];
    const float* self_w     = (const float*)d_in[6];
    const float* msg_w      = (const float*)d_in[7];
    const float* gate_w     = (const float*)d_in[8];
    const float* edge_w     = (const float*)d_in[9];
    const float* edge_b     = (const float*)d_in[10];
    const int*   species    = (const int*)d_in[11];
    const int*   ei         = (const int*)d_in[12];
    float* out = (float*)d_out;

    k_zero_sort<<<(NNODE + 255) / 256, 256>>>();
    k_count<<<NEDGE / 256, 256>>>(ei);
    k_scan<<<1, 1024>>>();
    k_fillgeom<<<NEDGE / 256, 256>>>(pos, ei);
    k_gemm1<<<NEDGE / 64, 256>>>(rw1, rb1);
    dim3 g2(NEDGE / 64, 2);
    k_gemm2<<<g2, 256>>>(rw2, rb2, edge_w, edge_b);
    k_initf<<<FTOT / 4 / 256, 256>>>(node_embed, species);

    int cur = 0;
    for (int t = 0; t < 3; t++) {
        k_gather<<<NNODE / 8, 256>>>(self_w, msg_w, gate_w, t, cur, out);
        k_nodeL<<<NB1 + NB2 + NB3, 256>>>(self_w, msg_w, t, cur, out);
        cur ^= 1;
    }

    k_edgeout<<<NEDGE / 8, 256>>>(out, cur);
}

// round 6
// speedup vs baseline: 1.3853x; 1.0964x over previous
#include <cuda_runtime.h>
#include <math.h>

typedef unsigned long long ull;

constexpr int NNODE = 10000;
constexpr int NEDGE = 160000;
constexpr int C = 32;
constexpr int H = 64;
constexpr int F_OFF1 = NNODE * C;
constexpr int F_OFF2 = 4 * NNODE * C;
constexpr int F_OFF3 = 9 * NNODE * C;
constexpr int FTOT   = 16 * NNODE * C;

// ---------------- scratch ---------------------------------------------------
__device__ float  g_h [(size_t)NEDGE * H];
__device__ float  g_w [(size_t)NEDGE * 384];
__device__ float  g_ew[(size_t)NEDGE * 128];
__device__ float  g_sh[(size_t)NEDGE * 16];
__device__ float2 g_geo[NEDGE];
__device__ float  g_f[2][FTOT];
__device__ float  g_agg[FTOT];
__device__ float  g_gate[NNODE * C];
__device__ int    g_cnt[NNODE];
__device__ int    g_fill[NNODE];
__device__ int    g_rowstart[NNODE + 1];
__device__ int    g_src[NEDGE];
__device__ int    g_dst[NEDGE];
__device__ int    g_orig[NEDGE];

__device__ __forceinline__ float siluf(float x) { return x / (1.0f + expf(-x)); }

__device__ __forceinline__ ull dup2(float a) {
    ull r;
    asm("mov.b64 %0, {%1, %1};" : "=l"(r) : "r"(__float_as_uint(a)));
    return r;
}
__device__ __forceinline__ void ffma2(ull& d, ull a, ull b) {
    asm("fma.rn.f32x2 %0, %1, %2, %0;" : "+l"(d) : "l"(a), "l"(b));
}
__device__ __forceinline__ float2 unpack2(ull v) {
    float2 f;
    asm("mov.b64 {%0, %1}, %2;" : "=f"(f.x), "=f"(f.y) : "l"(v));
    return f;
}

// ---------------- sorting: counting sort by dst ----------------------------
__global__ void k_zero_sort() {
    int i = blockIdx.x * 256 + threadIdx.x;
    if (i < NNODE) { g_cnt[i] = 0; g_fill[i] = 0; }
}
__global__ void k_count(const int* __restrict__ ei) {
    int e = blockIdx.x * 256 + threadIdx.x;
    atomicAdd(&g_cnt[ei[NEDGE + e]], 1);
}
__global__ void k_scan() {
    __shared__ int part[1024];
    int t = threadIdx.x;
    int base = t * 10;
    int vals[10];
    int s = 0;
#pragma unroll
    for (int i = 0; i < 10; i++) {
        int idx = base + i;
        int v = (idx < NNODE) ? g_cnt[idx] : 0;
        vals[i] = s; s += v;
    }
    part[t] = s;
    __syncthreads();
    for (int d = 1; d < 1024; d <<= 1) {
        int v = (t >= d) ? part[t - d] : 0;
        __syncthreads();
        part[t] += v;
        __syncthreads();
    }
    int off = (t == 0) ? 0 : part[t - 1];
#pragma unroll
    for (int i = 0; i < 10; i++) {
        int idx = base + i;
        if (idx < NNODE) g_rowstart[idx] = off + vals[i];
    }
    if (t == 1023) g_rowstart[NNODE] = part[1023];
}

__global__ void k_fillgeom(const float* __restrict__ pos, const int* __restrict__ ei) {
    int e = blockIdx.x * 256 + threadIdx.x;
    int s = ei[e], d = ei[NEDGE + e];
    int p = g_rowstart[d] + atomicAdd(&g_fill[d], 1);
    g_src[p] = s; g_dst[p] = d; g_orig[p] = e;
    float ax = pos[3 * s], ay = pos[3 * s + 1], az = pos[3 * s + 2];
    float bx = pos[3 * d], by = pos[3 * d + 1], bz = pos[3 * d + 2];
    float vx = bx - ax, vy = by - ay, vz = bz - az;
    float r = sqrtf(vx * vx + vy * vy + vz * vz + 1e-12f);
    float u = fminf(r * (1.0f / 5.0f), 1.0f);
    float env = 0.5f * (cospif(u) + 1.0f);
    g_geo[p] = make_float2(u, env * 0.63245553203f / r);
    float inv = 1.0f / r;
    float x = vx * inv, y = vy * inv, z = vz * inv;
    float x2 = x * x, y2 = y * y, z2 = z * z;
    float4* shp = reinterpret_cast<float4*>(g_sh + (size_t)p * 16);
    shp[0] = make_float4(1.0f, 1.7320508f * x, 1.7320508f * y, 1.7320508f * z);
    shp[1] = make_float4(3.87298335f * x * y, 3.87298335f * y * z,
                         1.11803399f * (3.0f * z2 - 1.0f), 3.87298335f * x * z);
    shp[2] = make_float4(1.93649167f * (x2 - y2),
                         2.09165007f * y * (3.0f * x2 - y2),
                         10.2469508f * x * y * z,
                         1.62018517f * y * (5.0f * z2 - 1.0f));
    shp[3] = make_float4(1.32287566f * (5.0f * z2 * z - 3.0f * z),
                         1.62018517f * x * (5.0f * z2 - 1.0f),
                         5.12347538f * z * (x2 - y2),
                         2.09165007f * x * (x2 - 3.0f * y2));
}

// ---------------- K2: h = silu(rb @ rw1 + rb1), recurrence fill ------------
__global__ __launch_bounds__(256) void k_gemm1(const float* __restrict__ rw1,
                                               const float* __restrict__ rb1) {
    __shared__ float  sA[64][68];   // stride 68 -> 16B aligned rows for LDS.128
    __shared__ float  sW[64][64];
    __shared__ float2 sG[64];
    int t  = threadIdx.x;
    int e0 = blockIdx.x * 64;
    if (t < 64) sG[t] = g_geo[e0 + t];
    ull acc[4][2];
#pragma unroll
    for (int i = 0; i < 4; i++) { acc[i][0] = 0ull; acc[i][1] = 0ull; }
    int row  = t & 63;
    int half = t >> 6;
    int jW = t & 63, kWb = t >> 6;
    int r0 = (t >> 4) << 2;
    int j0 = (t & 15) << 2;
    __syncthreads();
    float2 gg = sG[row];
    float s1, c1;
    sincospif(gg.x, &s1, &c1);
    float two = 2.0f * c1;
    for (int kk = 0; kk < 128; kk += 64) {
        if (kk) __syncthreads();
        {
            int n0 = kk + half * 16 + 1;
            float sa, ca;
            sincospif((float)n0 * gg.x, &sa, &ca);
            float sb = sa * c1 + ca * s1;
            int kloc = half * 16;
#pragma unroll
            for (int i = 0; i < 16; i++) {
                sA[kloc + i][row] = gg.y * sa;
                float sn = fmaf(two, sb, -sa);
                sa = sb; sb = sn;
            }
        }
#pragma unroll
        for (int i = 0; i < 16; i++) {
            int kr = kWb + (i << 2);
            sW[kr][jW] = rw1[(kk + kr) * 64 + jW];
        }
        __syncthreads();
#pragma unroll 8
        for (int k = 0; k < 64; k++) {
            float4 a4 = *reinterpret_cast<const float4*>(&sA[k][r0]);
            ull A0 = dup2(a4.x), A1 = dup2(a4.y), A2 = dup2(a4.z), A3 = dup2(a4.w);
            ulonglong2 bq = *reinterpret_cast<const ulonglong2*>(&sW[k][j0]);
            ull b0 = bq.x, b1 = bq.y;
            ffma2(acc[0][0], A0, b0); ffma2(acc[0][1], A0, b1);
            ffma2(acc[1][0], A1, b0); ffma2(acc[1][1], A1, b1);
            ffma2(acc[2][0], A2, b0); ffma2(acc[2][1], A2, b1);
            ffma2(acc[3][0], A3, b0); ffma2(acc[3][1], A3, b1);
        }
    }
    float4 bias = *reinterpret_cast<const float4*>(&rb1[j0]);
#pragma unroll
    for (int i = 0; i < 4; i++) {
        float2 lo = unpack2(acc[i][0]), hi = unpack2(acc[i][1]);
        float4 o;
        o.x = siluf(lo.x + bias.x); o.y = siluf(lo.y + bias.y);
        o.z = siluf(hi.x + bias.z); o.w = siluf(hi.y + bias.w);
        *reinterpret_cast<float4*>(&g_h[(size_t)(e0 + r0 + i) * 64 + j0]) = o;
    }
}

// ---------------- K3: [w_all | ew] = h @ [rw2 | edge_w] + bias -------------
__global__ __launch_bounds__(256) void k_gemm2(const float* __restrict__ rw2,
                                               const float* __restrict__ rb2,
                                               const float* __restrict__ edge_w,
                                               const float* __restrict__ edge_b) {
    __shared__ float sH[32][66];
    __shared__ float sW2[32][256];
    int t  = threadIdx.x;
    int e0 = blockIdx.x * 64;
    int cb = blockIdx.y << 8;
    int lane = t & 31;
    int r0 = lane << 1;
    int j0 = (t >> 5) << 5;
    ull acc[2][16];
#pragma unroll
    for (int i = 0; i < 2; i++)
#pragma unroll
        for (int j = 0; j < 16; j++) acc[i][j] = 0ull;
    int kh = t & 31, rb_ = (t >> 5) << 3;
    int colg = cb + t;
    for (int kk = 0; kk < 64; kk += 32) {
        __syncthreads();
#pragma unroll
        for (int i = 0; i < 8; i++)
            sH[kh][rb_ + i] = g_h[(size_t)(e0 + rb_ + i) * 64 + kk + kh];
#pragma unroll
        for (int kr = 0; kr < 32; kr++) {
            sW2[kr][t] = (colg < 384) ? rw2[(kk + kr) * 384 + colg]
                                      : edge_w[(kk + kr) * 128 + colg - 384];
        }
        __syncthreads();
#pragma unroll
        for (int k = 0; k < 32; k++) {
            ull a01 = *reinterpret_cast<const ull*>(&sH[k][r0]);
            float2 af = unpack2(a01);
            ull A0 = dup2(af.x), A1 = dup2(af.y);
            const ulonglong2* bq = reinterpret_cast<const ulonglong2*>(&sW2[k][j0]);
#pragma unroll
            for (int j = 0; j < 8; j++) {
                ulonglong2 q = bq[j];
                ffma2(acc[0][2 * j],     A0, q.x);
                ffma2(acc[0][2 * j + 1], A0, q.y);
                ffma2(acc[1][2 * j],     A1, q.x);
                ffma2(acc[1][2 * j + 1], A1, q.y);
            }
        }
    }
    bool inw = (cb + j0) < 384;
    const float* bsrc = inw ? (rb2 + cb + j0) : (edge_b + cb + j0 - 384);
#pragma unroll
    for (int i = 0; i < 2; i++) {
        int row = e0 + r0 + i;
        float* base = inw ? (g_w + (size_t)row * 384 + cb + j0)
                          : (g_ew + (size_t)row * 128 + cb + j0 - 384);
#pragma unroll
        for (int j = 0; j < 8; j++) {
            float2 p0 = unpack2(acc[i][2 * j]);
            float2 p1 = unpack2(acc[i][2 * j + 1]);
            float4 o = make_float4(p0.x + bsrc[4 * j],     p0.y + bsrc[4 * j + 1],
                                   p1.x + bsrc[4 * j + 2], p1.y + bsrc[4 * j + 3]);
            *reinterpret_cast<float4*>(base + 4 * j) = o;
        }
    }
}

// ---------------- init f[0] -------------------------------------------------
__global__ void k_initf(const float* __restrict__ node_embed,
                        const int* __restrict__ species) {
    int i4 = blockIdx.x * 256 + threadIdx.x;
    int idx = i4 * 4;
    float4 v;
    if (idx < NNODE * C) {
        int n = idx >> 5, c = idx & 31;
        v = *reinterpret_cast<const float4*>(&node_embed[(species[n] << 5) + c]);
    } else {
        v = make_float4(0.f, 0.f, 0.f, 0.f);
    }
    *reinterpret_cast<float4*>(&g_f[0][idx]) = v;
}

// ---------------- K4a: gather-aggregate + l0 update + gate -----------------
__global__ __launch_bounds__(256) void k_gather(const float* __restrict__ self_w,
                                                const float* __restrict__ msg_w,
                                                const float* __restrict__ gate_w,
                                                int t, int cur,
                                                float* __restrict__ out) {
    __shared__ float sS0[1024];
    __shared__ float sM0[1024];
    __shared__ float sGw[1024];
    int tid = threadIdx.x;
    for (int i = tid; i < 1024; i += 256) {
        sS0[i] = self_w[t * 4096 + i];
        sM0[i] = msg_w[t * 4096 + i];
        sGw[i] = gate_w[t * 1024 + i];
    }
    __syncthreads();
    int lane = tid & 31;
    int n = blockIdx.x * 8 + (tid >> 5);
    const float* fin = g_f[cur];
    float* fout = g_f[cur ^ 1];

    float acc[16];
#pragma unroll
    for (int i = 0; i < 16; i++) acc[i] = 0.0f;
    int row0 = g_rowstart[n], row1 = g_rowstart[n + 1];
#pragma unroll 2
    for (int row = row0; row < row1; row++) {
        float sv = fin[g_src[row] * C + lane];
        const float* wr = g_w + (size_t)row * 384 + t * 128;
        float w0 = wr[lane] * sv;
        float w1 = wr[32 + lane] * sv;
        float w2 = wr[64 + lane] * sv;
        float w3 = wr[96 + lane] * sv;
        const float4* shp = reinterpret_cast<const float4*>(g_sh + (size_t)row * 16);
        float4 s0 = shp[0], s1 = shp[1], s2 = shp[2], s3 = shp[3];
        acc[0]  += w0;
        acc[1]  = fmaf(w1, s0.y, acc[1]);
        acc[2]  = fmaf(w1, s0.z, acc[2]);
        acc[3]  = fmaf(w1, s0.w, acc[3]);
        acc[4]  = fmaf(w2, s1.x, acc[4]);
        acc[5]  = fmaf(w2, s1.y, acc[5]);
        acc[6]  = fmaf(w2, s1.z, acc[6]);
        acc[7]  = fmaf(w2, s1.w, acc[7]);
        acc[8]  = fmaf(w2, s2.x, acc[8]);
        acc[9]  = fmaf(w3, s2.y, acc[9]);
        acc[10] = fmaf(w3, s2.z, acc[10]);
        acc[11] = fmaf(w3, s2.w, acc[11]);
        acc[12] = fmaf(w3, s3.x, acc[12]);
        acc[13] = fmaf(w3, s3.y, acc[13]);
        acc[14] = fmaf(w3, s3.z, acc[14]);
        acc[15] = fmaf(w3, s3.w, acc[15]);
    }
    float* a1 = g_agg + F_OFF1 + n * 3 * C + lane;
    a1[0] = acc[1]; a1[32] = acc[2]; a1[64] = acc[3];
    float* a2 = g_agg + F_OFF2 + n * 5 * C + lane;
    a2[0] = acc[4]; a2[32] = acc[5]; a2[64] = acc[6]; a2[96] = acc[7]; a2[128] = acc[8];
    float* a3 = g_agg + F_OFF3 + n * 7 * C + lane;
    a3[0] = acc[9]; a3[32] = acc[10]; a3[64] = acc[11]; a3[96] = acc[12];
    a3[128] = acc[13]; a3[160] = acc[14]; a3[192] = acc[15];

    float fv = fin[n * C + lane];
    float a0 = 0.0f;
#pragma unroll
    for (int c = 0; c < 32; c++) {
        a0 = fmaf(__shfl_sync(0xffffffffu, fv, c), sS0[c * 32 + lane], a0);
        a0 = fmaf(__shfl_sync(0xffffffffu, acc[0], c), sM0[c * 32 + lane], a0);
    }
    float ga = 0.0f;
#pragma unroll
    for (int c = 0; c < 32; c++)
        ga = fmaf(__shfl_sync(0xffffffffu, a0, c), sGw[c * 32 + lane], ga);
    float gate = 1.0f / (1.0f + expf(-ga));
    float s0v = siluf(a0);
    fout[n * C + lane] = s0v;
    g_gate[n * C + lane] = gate;
    if (t == 2) out[(size_t)n * 512 + lane] = s0v;
}

// ---------------- K4b: l>=1 node update as dense GEMM ----------------------
constexpr int NB1 = (3 * NNODE + 63) / 64;
constexpr int NB2 = (5 * NNODE + 63) / 64;
constexpr int NB3 = (7 * NNODE + 63) / 64;
__global__ __launch_bounds__(256) void k_nodeL(const float* __restrict__ self_w,
                                               const float* __restrict__ msg_w,
                                               int t, int cur,
                                               float* __restrict__ out) {
    __shared__ float sF[32][68];
    __shared__ float sA[32][68];
    __shared__ float sWs[32][33];
    __shared__ float sWm[32][33];
    int bid = blockIdx.x;
    int l, row0, regrows, regbase;
    if (bid < NB1)            { l = 1; row0 = bid * 64;               regrows = 3 * NNODE; regbase = F_OFF1; }
    else if (bid < NB1 + NB2) { l = 2; row0 = (bid - NB1) * 64;       regrows = 5 * NNODE; regbase = F_OFF2; }
    else                      { l = 3; row0 = (bid - NB1 - NB2) * 64; regrows = 7 * NNODE; regbase = F_OFF3; }
    int tid = threadIdx.x;
    const float* fin = g_f[cur];
    float* fout = g_f[cur ^ 1];
    for (int i = tid; i < 1024; i += 256) {
        int c = i >> 5, d = i & 31;
        sWs[c][d] = self_w[t * 4096 + l * 1024 + i];
        sWm[c][d] = msg_w [t * 4096 + l * 1024 + i];
    }
    int nrows = min(64, regrows - row0);
    {
        int trow = tid >> 2, kh = tid & 3;
        float4 z = make_float4(0.f, 0.f, 0.f, 0.f);
        float4 v0 = z, v1 = z, w0 = z, w1 = z;
        if (trow < nrows) {
            const float4* fp = reinterpret_cast<const float4*>(fin + regbase + (size_t)(row0 + trow) * 32);
            const float4* ap = reinterpret_cast<const float4*>(g_agg + regbase + (size_t)(row0 + trow) * 32);
            v0 = fp[kh]; v1 = fp[kh + 4];
            w0 = ap[kh]; w1 = ap[kh + 4];
        }
        int k0 = kh * 4;
        sF[k0][trow] = v0.x; sF[k0 + 1][trow] = v0.y; sF[k0 + 2][trow] = v0.z; sF[k0 + 3][trow] = v0.w;
        sF[k0 + 16][trow] = v1.x; sF[k0 + 17][trow] = v1.y; sF[k0 + 18][trow] = v1.z; sF[k0 + 19][trow] = v1.w;
        sA[k0][trow] = w0.x; sA[k0 + 1][trow] = w0.y; sA[k0 + 2][trow] = w0.z; sA[k0 + 3][trow] = w0.w;
        sA[k0 + 16][trow] = w1.x; sA[k0 + 17][trow] = w1.y; sA[k0 + 18][trow] = w1.z; sA[k0 + 19][trow] = w1.w;
    }
    __syncthreads();
    int col = tid & 31, rg = tid >> 5;
    ull acc[4] = {0ull, 0ull, 0ull, 0ull};
#pragma unroll
    for (int k = 0; k < 32; k++) {
        const ulonglong2* fa = reinterpret_cast<const ulonglong2*>(&sF[k][rg * 8]);
        const ulonglong2* aa = reinterpret_cast<const ulonglong2*>(&sA[k][rg * 8]);
        ulonglong2 f01 = fa[0], f23 = fa[1];
        ulonglong2 a01 = aa[0], a23 = aa[1];
        ull bs = dup2(sWs[k][col]);
        ull bm = dup2(sWm[k][col]);
        ffma2(acc[0], f01.x, bs); ffma2(acc[0], a01.x, bm);
        ffma2(acc[1], f01.y, bs); ffma2(acc[1], a01.y, bm);
        ffma2(acc[2], f23.x, bs); ffma2(acc[2], a23.x, bm);
        ffma2(acc[3], f23.y, bs); ffma2(acc[3], a23.y, bm);
    }
    int r0 = rg * 8;
#pragma unroll
    for (int p = 0; p < 4; p++) {
        float2 v = unpack2(acc[p]);
        float vv[2] = {v.x, v.y};
#pragma unroll
        for (int j = 0; j < 2; j++) {
            int lrow = r0 + 2 * p + j;
            if (lrow >= nrows) continue;
            int grow = row0 + lrow;
            int node, m;
            if (l == 1)      { node = grow / 3; m = grow - node * 3; }
            else if (l == 2) { node = grow / 5; m = grow - node * 5; }
            else             { node = grow / 7; m = grow - node * 7; }
            float res = vv[j] * g_gate[node * C + col];
            if (t < 2) {
                fout[regbase + (size_t)grow * 32 + col] = res;
            } else {
                int colb = (l == 1) ? 32 : (l == 2) ? 128 : 288;
                out[(size_t)node * 512 + colb + col * (2 * l + 1) + m] = res;
            }
        }
    }
}

// ---------------- edge output: smem-staged coalesced stores ----------------
__global__ __launch_bounds__(256) void k_edgeout(float* __restrict__ out, int cur) {
    __shared__ float buf[8][512];
    int lane = threadIdx.x & 31;
    int w = threadIdx.x >> 5;
    int e = blockIdx.x * 8 + w;
    int s = g_src[e], d = g_dst[e];
    const float* f0 = g_f[cur];
    float gv = f0[s * C + lane] + f0[d * C + lane];
    const float* ewp = g_ew + (size_t)e * 128;
    float ew0 = ewp[lane], ew1 = ewp[32 + lane], ew2 = ewp[64 + lane], ew3 = ewp[96 + lane];
    const float4* shp = reinterpret_cast<const float4*>(g_sh + (size_t)e * 16);
    float4 s0 = shp[0], s1 = shp[1], s2 = shp[2], s3 = shp[3];
    float* base = buf[w];
    base[lane] = ew0 * gv;
    float w1 = ew1 * gv;
    float* p1 = base + 32 + lane * 3;
    p1[0] = w1 * s0.y; p1[1] = w1 * s0.z; p1[2] = w1 * s0.w;
    float w2 = ew2 * gv;
    float* p2 = base + 128 + lane * 5;
    p2[0] = w2 * s1.x; p2[1] = w2 * s1.y; p2[2] = w2 * s1.z;
    p2[3] = w2 * s1.w; p2[4] = w2 * s2.x;
    float w3 = ew3 * gv;
    float* p3 = base + 288 + lane * 7;
    p3[0] = w3 * s2.y; p3[1] = w3 * s2.z; p3[2] = w3 * s2.w;
    p3[3] = w3 * s3.x; p3[4] = w3 * s3.y; p3[5] = w3 * s3.z; p3[6] = w3 * s3.w;
    __syncwarp();
    // coalesced flush: this warp streams its own edge row as float4s
    const float4* src4 = reinterpret_cast<const float4*>(base);
    float4* dst4 = reinterpret_cast<float4*>(out + (size_t)(NNODE + g_orig[e]) * 512);
#pragma unroll
    for (int j = 0; j < 4; j++) dst4[lane + 32 * j] = src4[lane + 32 * j];
}

// ---------------- launch ----------------------------------------------------
extern "C" void kernel_launch(void* const* d_in, const int* in_sizes, int n_in,
                              void* d_out, int out_size) {
    const float* pos        = (const float*)d_in[0];
    const float* node_embed = (const float*)d_in[1];
    const float* rw1        = (const float*)d_in[2];
    const float* rb1        = (const float*)d_in[3];
    const float* rw2        = (const float*)d_in[4];
    const float* rb2        = (const float*)d_in[5];
    const float* self_w     = (const float*)d_in[6];
    const float* msg_w      = (const float*)d_in[7];
    const float* gate_w     = (const float*)d_in[8];
    const float* edge_w     = (const float*)d_in[9];
    const float* edge_b     = (const float*)d_in[10];
    const int*   species    = (const int*)d_in[11];
    const int*   ei         = (const int*)d_in[12];
    float* out = (float*)d_out;

    k_zero_sort<<<(NNODE + 255) / 256, 256>>>();
    k_count<<<NEDGE / 256, 256>>>(ei);
    k_scan<<<1, 1024>>>();
    k_fillgeom<<<NEDGE / 256, 256>>>(pos, ei);
    k_gemm1<<<NEDGE / 64, 256>>>(rw1, rb1);
    dim3 g2(NEDGE / 64, 2);
    k_gemm2<<<g2, 256>>>(rw2, rb2, edge_w, edge_b);
    k_initf<<<FTOT / 4 / 256, 256>>>(node_embed, species);

    int cur = 0;
    for (int t = 0; t < 3; t++) {
        k_gather<<<NNODE / 8, 256>>>(self_w, msg_w, gate_w, t, cur, out);
        k_nodeL<<<NB1 + NB2 + NB3, 256>>>(self_w, msg_w, t, cur, out);
        cur ^= 1;
    }

    k_edgeout<<<NEDGE / 8, 256>>>(out, cur);
}